// round 4
// baseline (speedup 1.0000x reference)
#include <cuda_runtime.h>

#define T_STEPS 20
#define N_NODES 32768
#define D_EMB   64
#define D_H     128
#define D_OUT   5
#define G4      (4*D_H)   // 512

#define MB       128      // nodes per block
#define NTHREADS 256
#define SROW     132      // padded shared row stride (floats), 16B-aligned, kills transpose conflicts

typedef unsigned long long ull;

__device__ __forceinline__ ull pk2(float v) {
    ull r; asm("mov.b64 %0, {%1, %1};" : "=l"(r) : "f"(v)); return r;
}
__device__ __forceinline__ ull f2fma(ull a, ull b, ull c) {
    ull d; asm("fma.rn.f32x2 %0, %1, %2, %3;" : "=l"(d) : "l"(a), "l"(b), "l"(c)); return d;
}
__device__ __forceinline__ float2 upk(ull a) {
    float2 f; asm("mov.b64 {%0, %1}, %2;" : "=f"(f.x), "=f"(f.y) : "l"(a)); return f;
}

__device__ __forceinline__ float sigm(float x) {
    return __fdividef(1.f, 1.f + __expf(-x));
}
__device__ __forceinline__ float tanh_(float x) {
    float ax = fabsf(x);
    float e  = __expf(-2.f * ax);           // in (0,1], overflow-safe
    float r  = __fdividef(1.f - e, 1.f + e);
    return copysignf(r, x);
}

// 4 nodes (packed pair a.x=[n0,n0+1], a.y=[n0+2,n0+3]) x 16 gate-outputs (4 ch x 4 gates)
#define GATE_FMA(aXY, Wbase) do {                                              \
    const float* Wr_ = (Wbase);                                                \
    float4 wq_[4];                                                             \
    wq_[0] = *(const float4*)(Wr_);                                            \
    wq_[1] = *(const float4*)(Wr_ + 128);                                      \
    wq_[2] = *(const float4*)(Wr_ + 256);                                      \
    wq_[3] = *(const float4*)(Wr_ + 384);                                      \
    _Pragma("unroll")                                                          \
    for (int g_ = 0; g_ < 4; ++g_) {                                           \
        const float* wf_ = (const float*)&wq_[g_];                             \
        _Pragma("unroll")                                                      \
        for (int ch_ = 0; ch_ < 4; ++ch_) {                                    \
            ull wp_ = pk2(wf_[ch_]);                                           \
            acc[g_][ch_][0] = f2fma((aXY).x, wp_, acc[g_][ch_][0]);            \
            acc[g_][ch_][1] = f2fma((aXY).y, wp_, acc[g_][ch_][1]);            \
        }                                                                      \
    }                                                                          \
} while (0)

__global__ void __launch_bounds__(NTHREADS, 1) vlstm_kernel(
    const float* __restrict__ nodes,          // (T, N, 2)
    const int* __restrict__ mask,             // (T, N) bool promoted to int32
    const float* __restrict__ h0,             // (N, 128)
    const float* __restrict__ c0,             // (N, 128)
    const float* __restrict__ W_embed,        // (2, 64)
    const float* __restrict__ b_embed,        // (64)
    const float* __restrict__ W_ih,           // (64, 512)
    const float* __restrict__ b_ih,           // (512)
    const float* __restrict__ W_hh,           // (128, 512)
    const float* __restrict__ b_hh,           // (512)
    const float* __restrict__ W_out,          // (128, 5)
    const float* __restrict__ b_out,          // (5)
    float* __restrict__ out)                  // outputs | h_fin | c_fin
{
    extern __shared__ float smem[];
    float* h_sh    = smem;                    // D_H  x SROW   (transposed: [k][node])
    float* c_sh    = h_sh  + D_H  * SROW;     // D_H  x SROW
    float* emb_sh  = c_sh  + D_H  * SROW;     // D_EMB x SROW
    float* mask_sh = emb_sh + D_EMB * SROW;   // MB

    const int tid   = threadIdx.x;
    const int gbase = blockIdx.x * MB;

    // ---- init h, c (coalesced gmem reads; 4-way-conflict smem writes, one-time) ----
    for (int idx = tid; idx < D_H * MB; idx += NTHREADS) {
        int node = idx >> 7;       // idx / 128
        int k    = idx & 127;
        h_sh[k * SROW + node] = h0[(size_t)(gbase + node) * D_H + k];
        c_sh[k * SROW + node] = c0[(size_t)(gbase + node) * D_H + k];
    }
    __syncthreads();

    const int warp  = tid >> 5;
    const int lane  = tid & 31;
    const int chW   = warp * 16;   // 16 channels per warp (8 warps x 16 = 128)
    const int n0    = lane * 4;    // 4 nodes per lane  (32 lanes x 4 = 128)
    const int nodeA = tid & (MB - 1);
    const int halfA = tid >> 7;    // 0 or 1

    for (int t = 0; t < T_STEPS; ++t) {
        // ---- Stage A: embedding + mask into shared ----
        {
            const float2 x = *(const float2*)&nodes[((size_t)t * N_NODES + gbase + nodeA) * 2];
            if (halfA == 0)
                mask_sh[nodeA] = (mask[(size_t)t * N_NODES + gbase + nodeA] != 0) ? 1.f : 0.f;
            #pragma unroll
            for (int ee = 0; ee < 32; ++ee) {
                int e = halfA * 32 + ee;
                float v = fmaf(x.x, W_embed[e], fmaf(x.y, W_embed[D_EMB + e], b_embed[e]));
                emb_sh[e * SROW + nodeA] = fmaxf(v, 0.f);
            }
        }
        __syncthreads();

        // ---- Stage B: gates + LSTM elementwise (c updated in place, h stashed) ----
        float hstash[4][4][4];    // [chunk][ch][node]
        #pragma unroll
        for (int cc = 0; cc < 4; ++cc) {
            const int ch0 = chW + cc * 4;
            ull acc[4][4][2];     // [gate][ch][node-pair]
            #pragma unroll
            for (int g = 0; g < 4; ++g)
                #pragma unroll
                for (int ch = 0; ch < 4; ++ch) { acc[g][ch][0] = 0ULL; acc[g][ch][1] = 0ULL; }

            #pragma unroll 2
            for (int k = 0; k < D_EMB; ++k) {
                ulonglong2 a = *(const ulonglong2*)&emb_sh[k * SROW + n0];
                GATE_FMA(a, W_ih + k * G4 + ch0);
            }
            #pragma unroll 2
            for (int k = 0; k < D_H; ++k) {
                ulonglong2 a = *(const ulonglong2*)&h_sh[k * SROW + n0];
                GATE_FMA(a, W_hh + k * G4 + ch0);
            }

            #pragma unroll
            for (int ch = 0; ch < 4; ++ch) {
                const int j  = ch0 + ch;
                const float bi = b_ih[j]       + b_hh[j];
                const float bf = b_ih[j + 128] + b_hh[j + 128];
                const float bg = b_ih[j + 256] + b_hh[j + 256];
                const float bo = b_ih[j + 384] + b_hh[j + 384];

                float iA[4], fA[4], gA[4], oA[4];
                { float2 p = upk(acc[0][ch][0]); iA[0]=p.x; iA[1]=p.y;
                  float2 q = upk(acc[0][ch][1]); iA[2]=q.x; iA[3]=q.y; }
                { float2 p = upk(acc[1][ch][0]); fA[0]=p.x; fA[1]=p.y;
                  float2 q = upk(acc[1][ch][1]); fA[2]=q.x; fA[3]=q.y; }
                { float2 p = upk(acc[2][ch][0]); gA[0]=p.x; gA[1]=p.y;
                  float2 q = upk(acc[2][ch][1]); gA[2]=q.x; gA[3]=q.y; }
                { float2 p = upk(acc[3][ch][0]); oA[0]=p.x; oA[1]=p.y;
                  float2 q = upk(acc[3][ch][1]); oA[2]=q.x; oA[3]=q.y; }

                #pragma unroll
                for (int n = 0; n < 4; ++n) {
                    float ival = sigm(iA[n] + bi);
                    float fval = sigm(fA[n] + bf);
                    float gval = tanh_(gA[n] + bg);
                    float oval = sigm(oA[n] + bo);
                    float cold = c_sh[j * SROW + n0 + n];
                    float cn   = fmaf(fval, cold, ival * gval);
                    float hn   = oval * tanh_(cn);
                    if (mask_sh[n0 + n] != 0.f) c_sh[j * SROW + n0 + n] = cn;
                    hstash[cc][ch][n] = hn;
                }
            }
        }
        __syncthreads();   // all h_sh reads of this step are done

        // ---- Stage C: masked h update ----
        #pragma unroll
        for (int cc = 0; cc < 4; ++cc)
            #pragma unroll
            for (int ch = 0; ch < 4; ++ch) {
                const int j = chW + cc * 4 + ch;
                #pragma unroll
                for (int n = 0; n < 4; ++n)
                    if (mask_sh[n0 + n] != 0.f)
                        h_sh[j * SROW + n0 + n] = hstash[cc][ch][n];
            }
        __syncthreads();

        // ---- Stage D: outputs (h_new @ W_out where mask, else 0) ----
        if (tid < MB) {
            const int node = tid;
            const size_t obase = (size_t)t * N_NODES * D_OUT + (size_t)(gbase + node) * D_OUT;
            if (mask_sh[node] != 0.f) {
                float o0 = b_out[0], o1 = b_out[1], o2 = b_out[2], o3 = b_out[3], o4 = b_out[4];
                #pragma unroll 4
                for (int k = 0; k < D_H; ++k) {
                    const float hv = h_sh[k * SROW + node];
                    const float* wr = W_out + k * D_OUT;
                    o0 = fmaf(hv, wr[0], o0);
                    o1 = fmaf(hv, wr[1], o1);
                    o2 = fmaf(hv, wr[2], o2);
                    o3 = fmaf(hv, wr[3], o3);
                    o4 = fmaf(hv, wr[4], o4);
                }
                out[obase + 0] = o0; out[obase + 1] = o1; out[obase + 2] = o2;
                out[obase + 3] = o3; out[obase + 4] = o4;
            } else {
                out[obase + 0] = 0.f; out[obase + 1] = 0.f; out[obase + 2] = 0.f;
                out[obase + 3] = 0.f; out[obase + 4] = 0.f;
            }
        }
        __syncthreads();   // protect mask_sh/emb_sh/h_sh before next step's writes
    }

    // ---- finals: h_fin, c_fin ----
    float* hfin = out + (size_t)T_STEPS * N_NODES * D_OUT;
    float* cfin = hfin + (size_t)N_NODES * D_H;
    for (int idx = tid; idx < D_H * MB; idx += NTHREADS) {
        int node = idx >> 7;
        int k    = idx & 127;
        hfin[(size_t)(gbase + node) * D_H + k] = h_sh[k * SROW + node];
        cfin[(size_t)(gbase + node) * D_H + k] = c_sh[k * SROW + node];
    }
}

extern "C" void kernel_launch(void* const* d_in, const int* in_sizes, int n_in,
                              void* d_out, int out_size)
{
    const float* nodes   = (const float*)d_in[0];
    const int*   mask    = (const int*)d_in[1];      // bool -> int32 in harness
    const float* h0      = (const float*)d_in[2];
    const float* c0      = (const float*)d_in[3];
    const float* W_embed = (const float*)d_in[4];
    const float* b_embed = (const float*)d_in[5];
    const float* W_ih    = (const float*)d_in[6];
    const float* b_ih    = (const float*)d_in[7];
    const float* W_hh    = (const float*)d_in[8];
    const float* b_hh    = (const float*)d_in[9];
    const float* W_out   = (const float*)d_in[10];
    const float* b_out   = (const float*)d_in[11];
    float* out = (float*)d_out;

    const size_t smem = (size_t)(2 * D_H * SROW + D_EMB * SROW + MB) * sizeof(float); // 169,472 B
    cudaFuncSetAttribute(vlstm_kernel, cudaFuncAttributeMaxDynamicSharedMemorySize, (int)smem);

    vlstm_kernel<<<N_NODES / MB, NTHREADS, smem>>>(
        nodes, mask, h0, c0, W_embed, b_embed, W_ih, b_ih, W_hh, b_hh, W_out, b_out, out);
}

// round 5
// speedup vs baseline: 1.6808x; 1.6808x over previous
#include <cuda_runtime.h>

#define T_STEPS 20
#define N_NODES 32768
#define D_EMB   64
#define D_H     128
#define D_OUT   5
#define G4      (4*D_H)   // 512

#define MB       128      // nodes per block
#define NT       512      // threads per block (16 warps)
#define SROW     128      // shared row stride (floats) — all hot accesses conflict-free

typedef unsigned long long ull;

// Precomputed embeddings, layout (T, D_EMB, N) so the recurrent kernel reads
// rows exactly like weight/h rows (node-contiguous, 16B aligned).
__device__ float g_emb[(size_t)T_STEPS * D_EMB * N_NODES];

__device__ __forceinline__ ull pk2(float v) {
    ull r; asm("mov.b64 %0, {%1, %1};" : "=l"(r) : "f"(v)); return r;
}
__device__ __forceinline__ ull f2fma(ull a, ull b, ull c) {
    ull d; asm("fma.rn.f32x2 %0, %1, %2, %3;" : "=l"(d) : "l"(a), "l"(b), "l"(c)); return d;
}
__device__ __forceinline__ float2 upk(ull a) {
    float2 f; asm("mov.b64 {%0, %1}, %2;" : "=f"(f.x), "=f"(f.y) : "l"(a)); return f;
}
__device__ __forceinline__ float sigm(float x) {
    return __fdividef(1.f, 1.f + __expf(-x));
}
__device__ __forceinline__ float tanh_(float x) {
    float ax = fabsf(x);
    float e  = __expf(-2.f * ax);
    float r  = __fdividef(1.f - e, 1.f + e);
    return copysignf(r, x);
}

// a = packed pair of 4 node activations; accumulate into 4 gates x 4 channels.
#define GATE_FMA(aXY, Wbase) do {                                              \
    const float* Wr_ = (Wbase);                                                \
    float4 wq_[4];                                                             \
    wq_[0] = *(const float4*)(Wr_);                                            \
    wq_[1] = *(const float4*)(Wr_ + 128);                                      \
    wq_[2] = *(const float4*)(Wr_ + 256);                                      \
    wq_[3] = *(const float4*)(Wr_ + 384);                                      \
    _Pragma("unroll")                                                          \
    for (int g_ = 0; g_ < 4; ++g_) {                                           \
        const float* wf_ = (const float*)&wq_[g_];                             \
        _Pragma("unroll")                                                      \
        for (int ch_ = 0; ch_ < 4; ++ch_) {                                    \
            ull wp_ = pk2(wf_[ch_]);                                           \
            acc[g_][ch_][0] = f2fma((aXY).x, wp_, acc[g_][ch_][0]);            \
            acc[g_][ch_][1] = f2fma((aXY).y, wp_, acc[g_][ch_][1]);            \
        }                                                                      \
    }                                                                          \
} while (0)

// ---------------- Kernel 1: embedding precompute ----------------
__global__ void __launch_bounds__(256) embed_kernel(
    const float* __restrict__ nodes,     // (T, N, 2)
    const float* __restrict__ W_embed,   // (2, 64)
    const float* __restrict__ b_embed)   // (64)
{
    const int n = blockIdx.x * 256 + threadIdx.x;
    const int t = blockIdx.y;
    const float2 x = ((const float2*)nodes)[(size_t)t * N_NODES + n];
    float* dst = g_emb + (size_t)t * D_EMB * N_NODES + n;
    #pragma unroll
    for (int e = 0; e < D_EMB; ++e) {
        float v = fmaf(x.x, __ldg(&W_embed[e]),
                  fmaf(x.y, __ldg(&W_embed[D_EMB + e]), __ldg(&b_embed[e])));
        dst[(size_t)e * N_NODES] = fmaxf(v, 0.f);
    }
}

// ---------------- Kernel 2: recurrent LSTM ----------------
__global__ void __launch_bounds__(NT, 1) vlstm_kernel(
    const int* __restrict__ maskg,            // (T, N) bool -> int32
    const float* __restrict__ h0,             // (N, 128)
    const float* __restrict__ c0,             // (N, 128)
    const float* __restrict__ W_ih,           // (64, 512)
    const float* __restrict__ b_ih,           // (512)
    const float* __restrict__ W_hh,           // (128, 512)
    const float* __restrict__ b_hh,           // (512)
    const float* __restrict__ W_out,          // (128, 5)
    const float* __restrict__ b_out,          // (5)
    float* __restrict__ out)                  // outputs | h_fin | c_fin
{
    extern __shared__ float smem[];
    float* hA      = smem;                         // 128 x 128  [k][node]
    float* hB      = hA + D_H * SROW;              // 128 x 128
    float* cS      = hB + D_H * SROW;              // 128 x 128
    float* mA      = cS + D_H * SROW;              // 128
    float* mB      = mA + MB;                      // 128
    float* bias_sh = mB + MB;                      // 512 (b_ih + b_hh)
    float* wout_sh = bias_sh + G4;                 // 640
    float* bout_sh = wout_sh + D_H * D_OUT;        // 8 (5 used)

    const int tid   = threadIdx.x;
    const int gbase = blockIdx.x * MB;

    // ---- init: h, c transposed into smem; bias/wout caches; mask t=0 ----
    for (int idx = tid; idx < D_H * MB; idx += NT) {
        int node = idx >> 7;
        int k    = idx & 127;
        hA[k * SROW + node] = h0[(size_t)(gbase + node) * D_H + k];
        cS[k * SROW + node] = c0[(size_t)(gbase + node) * D_H + k];
    }
    for (int i = tid; i < G4; i += NT) bias_sh[i] = b_ih[i] + b_hh[i];
    for (int i = tid; i < D_H * D_OUT; i += NT) wout_sh[i] = W_out[i];
    if (tid < D_OUT) bout_sh[tid] = b_out[tid];
    if (tid < MB) mA[tid] = (maskg[gbase + tid] != 0) ? 1.f : 0.f;
    __syncthreads();

    const int warp = tid >> 5;
    const int lane = tid & 31;
    const int n0   = lane * 4;          // 4 nodes per lane

    float* hc = hA;  float* hn = hB;
    float* mc = mA;  float* mn = mB;

    for (int t = 0; t < T_STEPS; ++t) {
        const float* eb = g_emb + (size_t)t * D_EMB * N_NODES + gbase + n0;

        #pragma unroll
        for (int cc = 0; cc < 2; ++cc) {
            const int ch0 = warp * 8 + cc * 4;
            ull acc[4][4][2];
            #pragma unroll
            for (int g = 0; g < 4; ++g)
                #pragma unroll
                for (int ch = 0; ch < 4; ++ch) { acc[g][ch][0] = 0ULL; acc[g][ch][1] = 0ULL; }

            #pragma unroll 2
            for (int k = 0; k < D_EMB; ++k) {
                ulonglong2 a = *(const ulonglong2*)(eb + (size_t)k * N_NODES);
                GATE_FMA(a, W_ih + k * G4 + ch0);
            }
            #pragma unroll 2
            for (int k = 0; k < D_H; ++k) {
                ulonglong2 a = *(const ulonglong2*)&hc[k * SROW + n0];
                GATE_FMA(a, W_hh + k * G4 + ch0);
            }

            const float4 m4 = *(const float4*)&mc[n0];
            const float mm[4] = { m4.x, m4.y, m4.z, m4.w };

            #pragma unroll
            for (int ch = 0; ch < 4; ++ch) {
                const int j  = ch0 + ch;
                const float bi = bias_sh[j];
                const float bf = bias_sh[j + 128];
                const float bg = bias_sh[j + 256];
                const float bo = bias_sh[j + 384];

                float iA[4], fA[4], gA[4], oA[4];
                { float2 p = upk(acc[0][ch][0]); iA[0]=p.x; iA[1]=p.y;
                  float2 q = upk(acc[0][ch][1]); iA[2]=q.x; iA[3]=q.y; }
                { float2 p = upk(acc[1][ch][0]); fA[0]=p.x; fA[1]=p.y;
                  float2 q = upk(acc[1][ch][1]); fA[2]=q.x; fA[3]=q.y; }
                { float2 p = upk(acc[2][ch][0]); gA[0]=p.x; gA[1]=p.y;
                  float2 q = upk(acc[2][ch][1]); gA[2]=q.x; gA[3]=q.y; }
                { float2 p = upk(acc[3][ch][0]); oA[0]=p.x; oA[1]=p.y;
                  float2 q = upk(acc[3][ch][1]); oA[2]=q.x; oA[3]=q.y; }

                const float4 cold4 = *(const float4*)&cS[j * SROW + n0];
                const float4 hold4 = *(const float4*)&hc[j * SROW + n0];
                const float coldA[4] = { cold4.x, cold4.y, cold4.z, cold4.w };
                const float holdA[4] = { hold4.x, hold4.y, hold4.z, hold4.w };

                float cnew[4], hnew[4];
                #pragma unroll
                for (int n = 0; n < 4; ++n) {
                    float ival = sigm(iA[n] + bi);
                    float fval = sigm(fA[n] + bf);
                    float gval = tanh_(gA[n] + bg);
                    float oval = sigm(oA[n] + bo);
                    float cn   = fmaf(fval, coldA[n], ival * gval);
                    float hv   = oval * tanh_(cn);
                    bool  m    = (mm[n] != 0.f);
                    cnew[n] = m ? cn : coldA[n];
                    hnew[n] = m ? hv : holdA[n];
                }
                *(float4*)&cS[j * SROW + n0] = make_float4(cnew[0], cnew[1], cnew[2], cnew[3]);
                *(float4*)&hn[j * SROW + n0] = make_float4(hnew[0], hnew[1], hnew[2], hnew[3]);
            }
        }

        // prefetch next step's mask (same threads that run Stage D -> race-free by program order)
        if (tid < MB && (t + 1) < T_STEPS)
            mn[tid] = (maskg[(size_t)(t + 1) * N_NODES + gbase + tid] != 0) ? 1.f : 0.f;

        __syncthreads();   // hn / cS complete; mn visible for next step

        // ---- Stage D: outputs for step t (reads hn = new h, mc = mask_t) ----
        if (tid < MB) {
            const int node = tid;
            const size_t obase = (size_t)t * N_NODES * D_OUT + (size_t)(gbase + node) * D_OUT;
            if (mc[node] != 0.f) {
                float o0 = bout_sh[0], o1 = bout_sh[1], o2 = bout_sh[2],
                      o3 = bout_sh[3], o4 = bout_sh[4];
                #pragma unroll 4
                for (int k = 0; k < D_H; ++k) {
                    const float hv = hn[k * SROW + node];
                    o0 = fmaf(hv, wout_sh[k * D_OUT + 0], o0);
                    o1 = fmaf(hv, wout_sh[k * D_OUT + 1], o1);
                    o2 = fmaf(hv, wout_sh[k * D_OUT + 2], o2);
                    o3 = fmaf(hv, wout_sh[k * D_OUT + 3], o3);
                    o4 = fmaf(hv, wout_sh[k * D_OUT + 4], o4);
                }
                out[obase + 0] = o0; out[obase + 1] = o1; out[obase + 2] = o2;
                out[obase + 3] = o3; out[obase + 4] = o4;
            } else {
                out[obase + 0] = 0.f; out[obase + 1] = 0.f; out[obase + 2] = 0.f;
                out[obase + 3] = 0.f; out[obase + 4] = 0.f;
            }
        }

        // swap ping-pong buffers
        float* tmp = hc; hc = hn; hn = tmp;
        float* tm  = mc; mc = mn; mn = tm;
    }

    // ---- finals: h_fin, c_fin (final h lives in hc after last swap) ----
    float* hfin = out + (size_t)T_STEPS * N_NODES * D_OUT;
    float* cfin = hfin + (size_t)N_NODES * D_H;
    for (int idx = tid; idx < D_H * MB; idx += NT) {
        int node = idx >> 7;
        int k    = idx & 127;
        hfin[(size_t)(gbase + node) * D_H + k] = hc[k * SROW + node];
        cfin[(size_t)(gbase + node) * D_H + k] = cS[k * SROW + node];
    }
}

extern "C" void kernel_launch(void* const* d_in, const int* in_sizes, int n_in,
                              void* d_out, int out_size)
{
    const float* nodes   = (const float*)d_in[0];
    const int*   mask    = (const int*)d_in[1];      // bool -> int32 in harness
    const float* h0      = (const float*)d_in[2];
    const float* c0      = (const float*)d_in[3];
    const float* W_embed = (const float*)d_in[4];
    const float* b_embed = (const float*)d_in[5];
    const float* W_ih    = (const float*)d_in[6];
    const float* b_ih    = (const float*)d_in[7];
    const float* W_hh    = (const float*)d_in[8];
    const float* b_hh    = (const float*)d_in[9];
    const float* W_out   = (const float*)d_in[10];
    const float* b_out   = (const float*)d_in[11];
    float* out = (float*)d_out;

    // Kernel 1: embeddings
    dim3 eg(N_NODES / 256, T_STEPS);
    embed_kernel<<<eg, 256>>>(nodes, W_embed, b_embed);

    // Kernel 2: recurrence
    const size_t smem = (size_t)(3 * D_H * SROW + 2 * MB + G4 + D_H * D_OUT + 8) * sizeof(float);
    cudaFuncSetAttribute(vlstm_kernel, cudaFuncAttributeMaxDynamicSharedMemorySize, (int)smem);
    vlstm_kernel<<<N_NODES / MB, NT, smem>>>(
        mask, h0, c0, W_ih, b_ih, W_hh, b_hh, W_out, b_out, out);
}